// round 15
// baseline (speedup 1.0000x reference)
#include <cuda_runtime.h>
#include <cuda_fp16.h>
#include <mma.h>
#include <cstdint>

using namespace nvcuda;

#define NT    256
#define NB    64
#define NLAY  4
#define NHID  1024
#define NCH   16       // K chunks of 128 halfs per stage (K = 2048)

// ---------------- device global scratch ----------------
__device__ __half   g_W[(size_t)NLAY * 32 * 2048 * 64];   // [(l*32+s)*2048 + k][64]; cols 0-31 learn, 32-63 forget
__device__ float    g_br[NLAY * 2048];                    // bias, paired cols
__device__ __half   g_X[(size_t)NT * NB * 1024];          // x fp16, plain [t][r][k]
__device__ __half   g_act[(size_t)NLAY * 257 * NB * 1024];// [l][slot][r][jg]; slot0 = h_init, slot t+1 = h(t)
__device__ unsigned g_flag[NLAY * NT * 32];               // per-(l,t,slice) completion flags (write-once)

// ---------------- helpers ----------------
__device__ __forceinline__ void cp16(uint32_t sdst, const void* gsrc) {
    asm volatile("cp.async.cg.shared.global [%0], [%1], 16;" :: "r"(sdst), "l"(gsrc));
}
// .noinc is load-bearing: the default form is count-neutral and deadlocks a
// barrier whose only arrivals are cp.async-tracked.
__device__ __forceinline__ void cp_mbar_arrive(uint32_t mbar) {
    asm volatile("cp.async.mbarrier.arrive.noinc.shared.b64 [%0];" :: "r"(mbar) : "memory");
}
__device__ __forceinline__ void mbar_init(uint32_t a, uint32_t cnt) {
    asm volatile("mbarrier.init.shared.b64 [%0], %1;" :: "r"(a), "r"(cnt) : "memory");
}
__device__ __forceinline__ void mbar_arrive(uint32_t a) {
    asm volatile("mbarrier.arrive.shared.b64 _, [%0];" :: "r"(a) : "memory");
}
__device__ __forceinline__ void mbar_wait(uint32_t a, uint32_t parity) {
    asm volatile(
        "{\n\t.reg .pred P;\n\tWL_%=: \n\t"
        "mbarrier.try_wait.parity.acquire.cta.shared::cta.b64 P, [%0], %1, 0x989680;\n\t"
        "@P bra.uni WD_%=;\n\tbra.uni WL_%=;\n\tWD_%=: \n\t}"
        :: "r"(a), "r"(parity) : "memory");
}
__device__ __forceinline__ void spin1(const unsigned* p) {
    unsigned x;
    do { asm volatile("ld.acquire.gpu.global.u32 %0, [%1];" : "=r"(x) : "l"(p) : "memory"); } while (x == 0);
}
// wait for the 4 consecutive slice flags covering one 128-wide K chunk
__device__ __forceinline__ void wait4(const unsigned* p) {
    spin1(p + 0); spin1(p + 1); spin1(p + 2); spin1(p + 3);
}
__device__ __forceinline__ void flag_set(unsigned* p) {
    asm volatile("st.release.gpu.global.u32 [%0], %1;" :: "l"(p), "r"(1u) : "memory");
}
__device__ __forceinline__ float tanh_fast(float x) {
    float y; asm("tanh.approx.f32 %0, %1;" : "=f"(y) : "f"(x)); return y;
}

// ---------------- prep kernels ----------------
__global__ void prep_weights(const float* __restrict__ W, const float* __restrict__ b) {
    long long i0 = (long long)blockIdx.x * 256 + threadIdx.x;
    if (i0 < NLAY * NT * 32) g_flag[i0] = 0;            // re-zero flags every launch
    if (i0 < NLAY * 2048) {
        int l = (int)(i0 >> 11), n = (int)(i0 & 2047);
        int s, c;
        if (n < NHID) { s = n >> 5; c = n & 31; }
        else          { s = (n - NHID) >> 5; c = 32 + ((n - NHID) & 31); }
        g_br[(l * 32 + s) * 64 + c] = b[i0];
    }
    const long long total = (long long)NLAY * 2048 * 2048;
    for (long long i = i0; i < total; i += (long long)gridDim.x * 256) {
        int n = (int)(i & 2047);
        int k = (int)((i >> 11) & 2047);
        int l = (int)(i >> 22);
        int s, c;
        if (n < NHID) { s = n >> 5; c = n & 31; }
        else          { s = (n - NHID) >> 5; c = 32 + ((n - NHID) & 31); }
        g_W[(((size_t)(l * 32 + s) * 2048 + k) << 6) + c] = __float2half(W[i]);
    }
}

__global__ void prep_states(const float* __restrict__ x, const float* __restrict__ h) {
    long long i0 = (long long)blockIdx.x * 256 + threadIdx.x;
    if (i0 < (long long)NLAY * NB * NHID) {   // h -> act[l][slot 0]
        int l = (int)(i0 >> 16);
        g_act[(size_t)l * 257 * 65536 + (i0 & 65535)] = __float2half(h[i0]);
    }
    const long long total = (long long)NT * NB * 1024;
    for (long long i = i0; i < total; i += (long long)gridDim.x * 256)
        g_X[i] = __float2half(x[i]);
}

// ---------------- main persistent kernel ----------------
// 128 blocks = 4 layers x 32 slices (64 paired cols each). 384 threads:
//   warps 0-7: wmma compute (K-split: warp w -> kk [(w>>2)*4,+4), tile ((w>>1)&1, w&1))
//   warps 8-11: cp.async producer + gate (sums both z partials).
// Cross-block deps: per-slice write-once flags; each 128-wide K chunk waits only
// on the 4 producer slices it actually reads.
#define AS_B  17408   // 64 x 136 halfs
#define WS_B  18432   // 128 x 72 halfs
#define ZS    4352    // 64 x 68 floats (one partial-z buffer)

__global__ void __launch_bounds__(384, 1) rnn_persistent(float* __restrict__ out, const float* __restrict__ h0) {
    extern __shared__ __align__(16) unsigned char dynsmem[];
    const uint32_t raw  = (uint32_t)__cvta_generic_to_shared(dynsmem);
    const uint32_t base = (raw + 1023u) & ~1023u;
    const uint32_t goff = base - raw;                 // generic-pointer offset of base

    const uint32_t full_mb  = base + 0;               // 4 x 8B
    const uint32_t free_mb  = base + 32;              // 4 x 8B
    const uint32_t zdone_mb = base + 64;              // 2 x 8B
    const uint32_t zfree_mb = base + 80;              // 2 x 8B
    const uint32_t As0 = base + 1024;                 // 4 x AS_B
    const uint32_t Ws0 = As0 + 4 * AS_B;              // 4 x WS_B
    __half* As_gen = (__half*)(dynsmem + goff + 1024);
    __half* Ws_gen = (__half*)(dynsmem + goff + 1024 + 4 * AS_B);
    // zbuf[tbuf 0/1][kgrp 0/1][64][68]
    float*  zbuf   = (float*)(dynsmem + goff + 1024 + 4 * AS_B + 4 * WS_B);

    const int tid = threadIdx.x;
    const int wid = tid >> 5;
    const int l = blockIdx.x >> 5;
    const int s = blockIdx.x & 31;

    if (tid == 0) {
        // full: 128 producer-thread .noinc arrivals; free/zdone: 256 compute
        // threads; zfree: 128 producer threads.
        for (int i = 0; i < 4; ++i) { mbar_init(full_mb + i * 8, 128); mbar_init(free_mb + i * 8, 256); }
        mbar_init(zdone_mb, 256); mbar_init(zdone_mb + 8, 256);
        mbar_init(zfree_mb, 128); mbar_init(zfree_mb + 8, 128);
    }
    __syncthreads();

    if (wid < 8) {
        // ================= compute: warps 0-7, K-split =================
        const int kgrp = wid >> 2;          // kk range [kgrp*4, kgrp*4+4)
        const int mi   = (wid >> 1) & 1;    // 32-row tile
        const int ni   = wid & 1;           // 32-col tile
        unsigned c = 0;
        for (int t = 0; t < NT; ++t) {
            wmma::fragment<wmma::accumulator, 16, 16, 16, float> acc[2][2];
#pragma unroll
            for (int i = 0; i < 2; ++i)
#pragma unroll
                for (int jj = 0; jj < 2; ++jj) wmma::fill_fragment(acc[i][jj], 0.f);

            for (int ch = 0; ch < NCH; ++ch, ++c) {
                const int slot = c & 3;
                const unsigned u = c >> 2;
                mbar_wait(full_mb + slot * 8, u & 1);
                const __half* as = As_gen + slot * (AS_B / 2);
                const __half* ws = Ws_gen + slot * (WS_B / 2);
#pragma unroll
                for (int k4 = 0; k4 < 4; ++k4) {
                    const int kk = kgrp * 4 + k4;
                    wmma::fragment<wmma::matrix_a, 16, 16, 16, __half, wmma::row_major> af0, af1;
                    wmma::fragment<wmma::matrix_b, 16, 16, 16, __half, wmma::row_major> bf0, bf1;
                    wmma::load_matrix_sync(af0, as + (mi * 32) * 136 + kk * 16, 136);
                    wmma::load_matrix_sync(af1, as + (mi * 32 + 16) * 136 + kk * 16, 136);
                    wmma::load_matrix_sync(bf0, ws + (kk * 16) * 72 + ni * 32, 72);
                    wmma::load_matrix_sync(bf1, ws + (kk * 16) * 72 + ni * 32 + 16, 72);
                    wmma::mma_sync(acc[0][0], af0, bf0, acc[0][0]);
                    wmma::mma_sync(acc[0][1], af0, bf1, acc[0][1]);
                    wmma::mma_sync(acc[1][0], af1, bf0, acc[1][0]);
                    wmma::mma_sync(acc[1][1], af1, bf1, acc[1][1]);
                }
                mbar_arrive(free_mb + slot * 8);
            }
            if (t >= 2) mbar_wait(zfree_mb + (t & 1) * 8, ((t - 2) >> 1) & 1);
            float* z = zbuf + (t & 1) * (2 * ZS) + kgrp * ZS;
#pragma unroll
            for (int i = 0; i < 2; ++i)
#pragma unroll
                for (int jj = 0; jj < 2; ++jj)
                    wmma::store_matrix_sync(z + (mi * 32 + i * 16) * 68 + ni * 32 + jj * 16,
                                            acc[i][jj], 68, wmma::mem_row_major);
            mbar_arrive(zdone_mb + (t & 1) * 8);
        }
    } else {
        // ================= producer + gate: warps 8-11 =================
        const int pid = tid - 256;                    // 0..127
        const int r   = pid >> 1;                     // gate row 0..63
        const int hf  = pid & 1;                      // col half
        const int j0  = hf * 16;
        const int jg0 = s * 32 + j0;
        const __half* Wbase = g_W + ((size_t)(l * 32 + s) << 17);

        float hreg[16], blv[16], bfv[16];
#pragma unroll
        for (int i = 0; i < 16; ++i) {
            blv[i]  = g_br[(l * 32 + s) * 64 + j0 + i];
            bfv[i]  = g_br[(l * 32 + s) * 64 + 32 + j0 + i];
            hreg[i] = h0[(size_t)(l * 64 + r) * 1024 + jg0 + i];
        }

        unsigned c = 0;
        auto produce = [&](const __half* asrc, int ch) {
            const int slot = c & 3;
            const unsigned u = c >> 2;
            if (u > 0) mbar_wait(free_mb + slot * 8, (u - 1) & 1);
            // A-side reads a 1024-wide source image at K offset (ch & 7)*128;
            // W-side indexes the full K=2048 directly (rows 1024+ = hidden weights).
            const int aoff = (ch & 7) * 128;
#pragma unroll
            for (int k8 = 0; k8 < 8; ++k8) {          // A: 64 x 128 halfs
                int i = pid + k8 * 128;
                int ar = i >> 4, c16 = i & 15;
                cp16(As0 + slot * AS_B + (ar * 136 + c16 * 8) * 2,
                     asrc + (size_t)ar * 1024 + aoff + c16 * 8);
            }
#pragma unroll
            for (int k8 = 0; k8 < 8; ++k8) {          // W: 128 x 64 halfs
                int i = pid + k8 * 128;
                int wr = i >> 3, c8 = i & 7;
                cp16(Ws0 + slot * WS_B + (wr * 72 + c8 * 8) * 2,
                     Wbase + (((size_t)(ch * 128 + wr)) << 6) + c8 * 8);
            }
            cp_mbar_arrive(full_mb + slot * 8);
            ++c;
        };
        auto produce_x = [&](int t) {                 // chunks 0-7: layer input at time t
            const __half* asrc = (l == 0) ? (g_X + (size_t)t * 65536)
                                          : (g_act + (((size_t)(l - 1) * 257 + t + 1) << 16));
            const unsigned* fb = (l > 0) ? &g_flag[((l - 1) * NT + t) * 32] : nullptr;
            for (int q = 0; q < 8; ++q) {
                if (fb) wait4(fb + 4 * q);            // only the 4 slices this chunk reads
                produce(asrc, q);
            }
        };
        auto produce_h = [&](int t) {                 // chunks 8-15: h(t-1) = act[l][slot t]
            const __half* asrc = g_act + (((size_t)l * 257 + t) << 16);
            const unsigned* fb = (t > 0) ? &g_flag[(l * NT + t - 1) * 32] : nullptr;
            for (int q = 0; q < 8; ++q) {
                if (fb) wait4(fb + 4 * q);            // per-chunk stagger vs gate stragglers
                produce(asrc, 8 + q);
            }
        };

        produce_x(0); produce_h(0);
        for (int t = 0; t < NT; ++t) {
            if (t + 1 < NT) produce_x(t + 1);         // overlap next stage's x-half with this gate

            mbar_wait(zdone_mb + (t & 1) * 8, (t >> 1) & 1);
            const float* z0 = zbuf + (t & 1) * (2 * ZS);
            const float* z1 = z0 + ZS;
            float zl[16], zf[16];
#pragma unroll
            for (int i = 0; i < 16; ++i) {
                zl[i] = z0[r * 68 + j0 + i]      + z1[r * 68 + j0 + i];
                zf[i] = z0[r * 68 + 32 + j0 + i] + z1[r * 68 + 32 + j0 + i];
            }
            mbar_arrive(zfree_mb + (t & 1) * 8);      // z buffers free for stage t+2

            __half* act = g_act + (((size_t)l * 257 + t + 1) << 16) + r * 1024 + jg0;
            float hv[16];
#pragma unroll
            for (int i = 0; i < 8; ++i) {
                float f0 = 1.f / (1.f + __expf(-(zf[2 * i]     + bfv[2 * i])));
                float f1 = 1.f / (1.f + __expf(-(zf[2 * i + 1] + bfv[2 * i + 1])));
                float h0v = fmaf(f0, hreg[2 * i],     (1.f - f0) * tanh_fast(zl[2 * i]     + blv[2 * i]));
                float h1v = fmaf(f1, hreg[2 * i + 1], (1.f - f1) * tanh_fast(zl[2 * i + 1] + blv[2 * i + 1]));
                hreg[2 * i] = h0v; hreg[2 * i + 1] = h1v;
                hv[2 * i] = h0v; hv[2 * i + 1] = h1v;
                *(__half2*)(act + 2 * i) = __halves2half2(__float2half(h0v), __float2half(h1v));
            }
            // release own slice flag ASAP (before the l==3 output store)
            asm volatile("bar.sync 1, 128;" ::: "memory");   // gate warps: all act stores issued
            if (pid == 0) { __threadfence(); flag_set(&g_flag[(l * NT + t) * 32 + s]); }

            if (l == 3) {
                float4* ob = (float4*)(out + (size_t)(t * 64 + r) * 1024 + jg0);
#pragma unroll
                for (int q = 0; q < 4; ++q)
                    ob[q] = make_float4(hv[4 * q], hv[4 * q + 1], hv[4 * q + 2], hv[4 * q + 3]);
            }

            if (t + 1 < NT) produce_h(t + 1);         // per-chunk flag waits inside
        }
        // h_final appended after outputs
        float4* ob = (float4*)(out + (size_t)NT * NB * NHID + (size_t)(l * 64 + r) * 1024 + jg0);
#pragma unroll
        for (int q = 0; q < 4; ++q)
            ob[q] = make_float4(hreg[4 * q], hreg[4 * q + 1], hreg[4 * q + 2], hreg[4 * q + 3]);
    }
}

// ---------------- launch ----------------
extern "C" void kernel_launch(void* const* d_in, const int* in_sizes, int n_in,
                              void* d_out, int out_size) {
    const float* x = (const float*)d_in[0];
    const float* h = (const float*)d_in[1];
    const float* W = (const float*)d_in[2];
    const float* b = (const float*)d_in[3];
    float* out = (float*)d_out;

    // dyn smem: 1024 slack + 1024 mbars + 4*AS_B + 4*WS_B + 4*ZS*4 = 215040
    const int dynsmem = 1024 + 1024 + 4 * AS_B + 4 * WS_B + 4 * ZS * 4;
    static int attr_set = 0;
    if (!attr_set) {
        cudaFuncSetAttribute(rnn_persistent, cudaFuncAttributeMaxDynamicSharedMemorySize, dynsmem);
        attr_set = 1;
    }

    prep_weights<<<4096, 256>>>(W, b);
    prep_states<<<4096, 256>>>(x, h);
    rnn_persistent<<<128, 384, dynsmem>>>(out, h);
}

// round 16
// speedup vs baseline: 2.1566x; 2.1566x over previous
#include <cuda_runtime.h>
#include <cuda_fp16.h>
#include <mma.h>
#include <cstdint>

using namespace nvcuda;

#define NT    256
#define NB    64
#define NLAY  4
#define NHID  1024
#define NCH   16       // K chunks of 128 halfs per stage (K = 2048)

// ---------------- device global scratch ----------------
__device__ __half   g_W[(size_t)NLAY * 32 * 2048 * 64];   // [(l*32+s)*2048 + k][64]; cols 0-31 learn, 32-63 forget
__device__ float    g_br[NLAY * 2048];                    // bias, paired cols
__device__ __half   g_X[(size_t)NT * NB * 1024];          // x fp16, plain [t][r][k]
__device__ __half   g_act[(size_t)NLAY * 257 * NB * 1024];// [l][slot][r][jg]; slot0 = h_init, slot t+1 = h(t)
__device__ unsigned g_done[NLAY * NT];                    // per-(layer,t) completion counters

// ---------------- helpers ----------------
__device__ __forceinline__ void cp16(uint32_t sdst, const void* gsrc) {
    asm volatile("cp.async.cg.shared.global [%0], [%1], 16;" :: "r"(sdst), "l"(gsrc));
}
// .noinc is load-bearing: the default form is count-neutral and deadlocks a
// barrier whose only arrivals are cp.async-tracked.
__device__ __forceinline__ void cp_mbar_arrive(uint32_t mbar) {
    asm volatile("cp.async.mbarrier.arrive.noinc.shared.b64 [%0];" :: "r"(mbar) : "memory");
}
__device__ __forceinline__ void mbar_init(uint32_t a, uint32_t cnt) {
    asm volatile("mbarrier.init.shared.b64 [%0], %1;" :: "r"(a), "r"(cnt) : "memory");
}
__device__ __forceinline__ void mbar_arrive(uint32_t a) {
    asm volatile("mbarrier.arrive.shared.b64 _, [%0];" :: "r"(a) : "memory");
}
__device__ __forceinline__ void mbar_wait(uint32_t a, uint32_t parity) {
    asm volatile(
        "{\n\t.reg .pred P;\n\tWL_%=: \n\t"
        "mbarrier.try_wait.parity.acquire.cta.shared::cta.b64 P, [%0], %1, 0x989680;\n\t"
        "@P bra.uni WD_%=;\n\tbra.uni WL_%=;\n\tWD_%=: \n\t}"
        :: "r"(a), "r"(parity) : "memory");
}
__device__ __forceinline__ void spin_ge(const unsigned* p, unsigned v) {
    unsigned x;
    do { asm volatile("ld.acquire.gpu.global.u32 %0, [%1];" : "=r"(x) : "l"(p) : "memory"); } while (x < v);
}
__device__ __forceinline__ float tanh_fast(float x) {
    float y; asm("tanh.approx.f32 %0, %1;" : "=f"(y) : "f"(x)); return y;
}

// ---------------- prep kernels ----------------
__global__ void prep_weights(const float* __restrict__ W, const float* __restrict__ b) {
    long long i0 = (long long)blockIdx.x * 256 + threadIdx.x;
    if (i0 < NLAY * NT) g_done[i0] = 0;                 // re-zero counters every launch
    if (i0 < NLAY * 2048) {
        int l = (int)(i0 >> 11), n = (int)(i0 & 2047);
        int s, c;
        if (n < NHID) { s = n >> 5; c = n & 31; }
        else          { s = (n - NHID) >> 5; c = 32 + ((n - NHID) & 31); }
        g_br[(l * 32 + s) * 64 + c] = b[i0];
    }
    const long long total = (long long)NLAY * 2048 * 2048;
    for (long long i = i0; i < total; i += (long long)gridDim.x * 256) {
        int n = (int)(i & 2047);
        int k = (int)((i >> 11) & 2047);
        int l = (int)(i >> 22);
        int s, c;
        if (n < NHID) { s = n >> 5; c = n & 31; }
        else          { s = (n - NHID) >> 5; c = 32 + ((n - NHID) & 31); }
        g_W[(((size_t)(l * 32 + s) * 2048 + k) << 6) + c] = __float2half(W[i]);
    }
}

__global__ void prep_states(const float* __restrict__ x, const float* __restrict__ h) {
    long long i0 = (long long)blockIdx.x * 256 + threadIdx.x;
    if (i0 < (long long)NLAY * NB * NHID) {   // h -> act[l][slot 0]
        int l = (int)(i0 >> 16);
        g_act[(size_t)l * 257 * 65536 + (i0 & 65535)] = __float2half(h[i0]);
    }
    const long long total = (long long)NT * NB * 1024;
    for (long long i = i0; i < total; i += (long long)gridDim.x * 256)
        g_X[i] = __float2half(x[i]);
}

// ---------------- main persistent kernel ----------------
// 128 blocks = 4 layers x 32 slices (64 paired cols each). 384 threads:
//   warps 0-7: wmma compute (K-split: warp w -> kk [(w>>2)*4,+4), tile ((w>>1)&1, w&1))
//              Per chunk: load ALL fragments to registers, release the ring slot
//              EARLY (mbar_arrive before the mma phase), then issue 16 mma_syncs.
//   warps 8-11: cp.async producer + gate (sums both z partials).
// Cross-block deps: single atomicAdd counter per (l,t), one spin per produce phase.
#define AS_B  17408   // 64 x 136 halfs
#define WS_B  18432   // 128 x 72 halfs
#define ZS    4352    // 64 x 68 floats (one partial-z buffer)

__global__ void __launch_bounds__(384, 1) rnn_persistent(float* __restrict__ out, const float* __restrict__ h0) {
    extern __shared__ __align__(16) unsigned char dynsmem[];
    const uint32_t raw  = (uint32_t)__cvta_generic_to_shared(dynsmem);
    const uint32_t base = (raw + 1023u) & ~1023u;
    const uint32_t goff = base - raw;                 // generic-pointer offset of base

    const uint32_t full_mb  = base + 0;               // 4 x 8B
    const uint32_t free_mb  = base + 32;              // 4 x 8B
    const uint32_t zdone_mb = base + 64;              // 2 x 8B
    const uint32_t zfree_mb = base + 80;              // 2 x 8B
    const uint32_t As0 = base + 1024;                 // 4 x AS_B
    const uint32_t Ws0 = As0 + 4 * AS_B;              // 4 x WS_B
    __half* As_gen = (__half*)(dynsmem + goff + 1024);
    __half* Ws_gen = (__half*)(dynsmem + goff + 1024 + 4 * AS_B);
    // zbuf[tbuf 0/1][kgrp 0/1][64][68]
    float*  zbuf   = (float*)(dynsmem + goff + 1024 + 4 * AS_B + 4 * WS_B);

    const int tid = threadIdx.x;
    const int wid = tid >> 5;
    const int l = blockIdx.x >> 5;
    const int s = blockIdx.x & 31;

    if (tid == 0) {
        // full: 128 producer-thread .noinc arrivals; free/zdone: 256 compute
        // threads; zfree: 128 producer threads.
        for (int i = 0; i < 4; ++i) { mbar_init(full_mb + i * 8, 128); mbar_init(free_mb + i * 8, 256); }
        mbar_init(zdone_mb, 256); mbar_init(zdone_mb + 8, 256);
        mbar_init(zfree_mb, 128); mbar_init(zfree_mb + 8, 128);
    }
    __syncthreads();

    if (wid < 8) {
        // ================= compute: warps 0-7, K-split =================
        const int kgrp = wid >> 2;          // kk range [kgrp*4, kgrp*4+4)
        const int mi   = (wid >> 1) & 1;    // 32-row tile
        const int ni   = wid & 1;           // 32-col tile
        unsigned c = 0;
        for (int t = 0; t < NT; ++t) {
            wmma::fragment<wmma::accumulator, 16, 16, 16, float> acc[2][2];
#pragma unroll
            for (int i = 0; i < 2; ++i)
#pragma unroll
                for (int jj = 0; jj < 2; ++jj) wmma::fill_fragment(acc[i][jj], 0.f);

            for (int ch = 0; ch < NCH; ++ch, ++c) {
                const int slot = c & 3;
                const unsigned u = c >> 2;
                mbar_wait(full_mb + slot * 8, u & 1);
                const __half* as = As_gen + slot * (AS_B / 2);
                const __half* ws = Ws_gen + slot * (WS_B / 2);

                // ---- phase 1: pull the whole chunk into registers ----
                wmma::fragment<wmma::matrix_a, 16, 16, 16, __half, wmma::row_major> af[4][2];
                wmma::fragment<wmma::matrix_b, 16, 16, 16, __half, wmma::row_major> bf[4][2];
#pragma unroll
                for (int k4 = 0; k4 < 4; ++k4) {
                    const int kk = kgrp * 4 + k4;
                    wmma::load_matrix_sync(af[k4][0], as + (mi * 32) * 136 + kk * 16, 136);
                    wmma::load_matrix_sync(af[k4][1], as + (mi * 32 + 16) * 136 + kk * 16, 136);
                    wmma::load_matrix_sync(bf[k4][0], ws + (kk * 16) * 72 + ni * 32, 72);
                    wmma::load_matrix_sync(bf[k4][1], ws + (kk * 16) * 72 + ni * 32 + 16, 72);
                }
                // ---- early release: slot refillable while we do the math ----
                mbar_arrive(free_mb + slot * 8);

                // ---- phase 2: 16 mma_syncs from registers ----
#pragma unroll
                for (int k4 = 0; k4 < 4; ++k4) {
                    wmma::mma_sync(acc[0][0], af[k4][0], bf[k4][0], acc[0][0]);
                    wmma::mma_sync(acc[0][1], af[k4][0], bf[k4][1], acc[0][1]);
                    wmma::mma_sync(acc[1][0], af[k4][1], bf[k4][0], acc[1][0]);
                    wmma::mma_sync(acc[1][1], af[k4][1], bf[k4][1], acc[1][1]);
                }
            }
            if (t >= 2) mbar_wait(zfree_mb + (t & 1) * 8, ((t - 2) >> 1) & 1);
            float* z = zbuf + (t & 1) * (2 * ZS) + kgrp * ZS;
#pragma unroll
            for (int i = 0; i < 2; ++i)
#pragma unroll
                for (int jj = 0; jj < 2; ++jj)
                    wmma::store_matrix_sync(z + (mi * 32 + i * 16) * 68 + ni * 32 + jj * 16,
                                            acc[i][jj], 68, wmma::mem_row_major);
            mbar_arrive(zdone_mb + (t & 1) * 8);
        }
    } else {
        // ================= producer + gate: warps 8-11 =================
        const int pid = tid - 256;                    // 0..127
        const int r   = pid >> 1;                     // gate row 0..63
        const int hf  = pid & 1;                      // col half
        const int j0  = hf * 16;
        const int jg0 = s * 32 + j0;
        const __half* Wbase = g_W + ((size_t)(l * 32 + s) << 17);

        float hreg[16], blv[16], bfv[16];
#pragma unroll
        for (int i = 0; i < 16; ++i) {
            blv[i]  = g_br[(l * 32 + s) * 64 + j0 + i];
            bfv[i]  = g_br[(l * 32 + s) * 64 + 32 + j0 + i];
            hreg[i] = h0[(size_t)(l * 64 + r) * 1024 + jg0 + i];
        }

        unsigned c = 0;
        auto produce = [&](const __half* asrc, int ch) {
            const int slot = c & 3;
            const unsigned u = c >> 2;
            if (u > 0) mbar_wait(free_mb + slot * 8, (u - 1) & 1);
            // A-side reads a 1024-wide source image at K offset (ch & 7)*128;
            // W-side indexes the full K=2048 directly (rows 1024+ = hidden weights).
            const int aoff = (ch & 7) * 128;
#pragma unroll
            for (int k8 = 0; k8 < 8; ++k8) {          // A: 64 x 128 halfs
                int i = pid + k8 * 128;
                int ar = i >> 4, c16 = i & 15;
                cp16(As0 + slot * AS_B + (ar * 136 + c16 * 8) * 2,
                     asrc + (size_t)ar * 1024 + aoff + c16 * 8);
            }
#pragma unroll
            for (int k8 = 0; k8 < 8; ++k8) {          // W: 128 x 64 halfs
                int i = pid + k8 * 128;
                int wr = i >> 3, c8 = i & 7;
                cp16(Ws0 + slot * WS_B + (wr * 72 + c8 * 8) * 2,
                     Wbase + (((size_t)(ch * 128 + wr)) << 6) + c8 * 8);
            }
            cp_mbar_arrive(full_mb + slot * 8);
            ++c;
        };
        auto produce_x = [&](int t) {                 // chunks 0-7: layer input at time t
            const __half* asrc = (l == 0) ? (g_X + (size_t)t * 65536)
                                          : (g_act + (((size_t)(l - 1) * 257 + t + 1) << 16));
            if (l > 0) spin_ge(&g_done[(l - 1) * NT + t], 32);
            for (int ch = 0; ch < 8; ++ch) produce(asrc, ch);
        };
        auto produce_h = [&](int t) {                 // chunks 8-15: h(t-1) = act[l][slot t]
            // Full 1024-wide K operand carries contributions from ALL 32
            // slice-blocks of this layer -> wait for the whole layer's gate at t-1.
            if (t > 0) spin_ge(&g_done[l * NT + t - 1], 32);
            const __half* asrc = g_act + (((size_t)l * 257 + t) << 16);
            for (int ch = 8; ch < 16; ++ch) produce(asrc, ch);
        };

        produce_x(0); produce_h(0);
        for (int t = 0; t < NT; ++t) {
            if (t + 1 < NT) produce_x(t + 1);         // overlap next stage's x-half with this gate

            mbar_wait(zdone_mb + (t & 1) * 8, (t >> 1) & 1);
            const float* z0 = zbuf + (t & 1) * (2 * ZS);
            const float* z1 = z0 + ZS;
            float zl[16], zf[16];
#pragma unroll
            for (int i = 0; i < 16; ++i) {
                zl[i] = z0[r * 68 + j0 + i]      + z1[r * 68 + j0 + i];
                zf[i] = z0[r * 68 + 32 + j0 + i] + z1[r * 68 + 32 + j0 + i];
            }
            mbar_arrive(zfree_mb + (t & 1) * 8);      // z buffers free for stage t+2

            __half* act = g_act + (((size_t)l * 257 + t + 1) << 16) + r * 1024 + jg0;
            float hv[16];
#pragma unroll
            for (int i = 0; i < 8; ++i) {
                float f0 = 1.f / (1.f + __expf(-(zf[2 * i]     + bfv[2 * i])));
                float f1 = 1.f / (1.f + __expf(-(zf[2 * i + 1] + bfv[2 * i + 1])));
                float h0v = fmaf(f0, hreg[2 * i],     (1.f - f0) * tanh_fast(zl[2 * i]     + blv[2 * i]));
                float h1v = fmaf(f1, hreg[2 * i + 1], (1.f - f1) * tanh_fast(zl[2 * i + 1] + blv[2 * i + 1]));
                hreg[2 * i] = h0v; hreg[2 * i + 1] = h1v;
                hv[2 * i] = h0v; hv[2 * i + 1] = h1v;
                *(__half2*)(act + 2 * i) = __halves2half2(__float2half(h0v), __float2half(h1v));
            }
            // release layer-done counter ASAP (act stores issued; out store after)
            asm volatile("bar.sync 1, 128;" ::: "memory");   // gate warps only
            if (pid == 0) { __threadfence(); atomicAdd(&g_done[l * NT + t], 1u); }

            if (l == 3) {
                float4* ob = (float4*)(out + (size_t)(t * 64 + r) * 1024 + jg0);
#pragma unroll
                for (int q = 0; q < 4; ++q)
                    ob[q] = make_float4(hv[4 * q], hv[4 * q + 1], hv[4 * q + 2], hv[4 * q + 3]);
            }

            if (t + 1 < NT) produce_h(t + 1);         // waits whole-layer done(t) inside
        }
        // h_final appended after outputs
        float4* ob = (float4*)(out + (size_t)NT * NB * NHID + (size_t)(l * 64 + r) * 1024 + jg0);
#pragma unroll
        for (int q = 0; q < 4; ++q)
            ob[q] = make_float4(hreg[4 * q], hreg[4 * q + 1], hreg[4 * q + 2], hreg[4 * q + 3]);
    }
}

// ---------------- launch ----------------
extern "C" void kernel_launch(void* const* d_in, const int* in_sizes, int n_in,
                              void* d_out, int out_size) {
    const float* x = (const float*)d_in[0];
    const float* h = (const float*)d_in[1];
    const float* W = (const float*)d_in[2];
    const float* b = (const float*)d_in[3];
    float* out = (float*)d_out;

    // dyn smem: 1024 slack + 1024 mbars + 4*AS_B + 4*WS_B + 4*ZS*4 = 215040
    const int dynsmem = 1024 + 1024 + 4 * AS_B + 4 * WS_B + 4 * ZS * 4;
    static int attr_set = 0;
    if (!attr_set) {
        cudaFuncSetAttribute(rnn_persistent, cudaFuncAttributeMaxDynamicSharedMemorySize, dynsmem);
        attr_set = 1;
    }

    prep_weights<<<4096, 256>>>(W, b);
    prep_states<<<4096, 256>>>(x, h);
    rnn_persistent<<<128, 384, dynsmem>>>(out, h);
}